// round 9
// baseline (speedup 1.0000x reference)
#include <cuda_runtime.h>
#include <cuda_bf16.h>

// ---------------- problem constants ----------------
constexpr int N_NODES  = 50000;
constexpr int N_EDGES  = 100000;
constexpr int N_GRAPHS = 2000;
constexpr int IN_DIM   = 32;
constexpr int EDGE_DIM = 8;
constexpr int HID      = 64;
constexpr int N_TASKS  = 12;
constexpr float BN_EPS = 1e-5f;

typedef unsigned long long ull;
constexpr ull ABS2 = 0x7FFFFFFF7FFFFFFFULL;

// ---------------- packed f32x2 helpers ----------------
__device__ __forceinline__ ull pack2(float lo, float hi) {
    ull r; asm("mov.b64 %0, {%1,%2};" : "=l"(r) : "f"(lo), "f"(hi)); return r;
}
__device__ __forceinline__ ull dup2(float v) {
    ull r; asm("mov.b64 %0, {%1,%1};" : "=l"(r) : "f"(v)); return r;
}
__device__ __forceinline__ void unpack2(ull v, float& lo, float& hi) {
    asm("mov.b64 {%0,%1}, %2;" : "=f"(lo), "=f"(hi) : "l"(v));
}
__device__ __forceinline__ ull fma2(ull a, ull b, ull c) {
    ull d; asm("fma.rn.f32x2 %0, %1, %2, %3;" : "=l"(d) : "l"(a), "l"(b), "l"(c)); return d;
}
__device__ __forceinline__ ull add2(ull a, ull b) {
    ull d; asm("add.rn.f32x2 %0, %1, %2;" : "=l"(d) : "l"(a), "l"(b)); return d;
}

// ---------------- scratch (device globals; no allocation allowed) -----------
__device__ float g_h1[N_NODES * HID];
__device__ float g_h2[N_NODES * HID];
__device__ float g_aggr[N_NODES * HID];   // zero .bss; node kernels restore zeros
__device__ float g_deg[N_NODES];          // reciprocal after k_recip
__device__ float g_cnt[N_GRAPHS];         // reciprocal after k_recip
__device__ float g_bn[2 * HID];
__device__ float g_pool[N_GRAPHS * HID];

// ---------------- init / counts / recip ----------------
__global__ void k_init() {
    int i = blockIdx.x * 256 + threadIdx.x;
    if (i < N_NODES)        g_deg[i] = 0.f;
    if (i < N_GRAPHS * HID) g_pool[i] = 0.f;
    if (i < N_GRAPHS)       g_cnt[i] = 0.f;
    if (i < 2 * HID)        g_bn[i] = 0.f;
}

__global__ void k_counts(const int* __restrict__ ei, const int* __restrict__ batch) {
    int i = blockIdx.x * 256 + threadIdx.x;
    if (i < N_EDGES) atomicAdd(&g_deg[ei[N_EDGES + i]], 1.f);
    if (i < N_NODES) atomicAdd(&g_cnt[batch[i]], 1.f);
}

__global__ void k_recip() {
    int i = blockIdx.x * 256 + threadIdx.x;
    if (i < N_NODES)  g_deg[i] = 1.f / fmaxf(g_deg[i], 1.f);
    if (i < N_GRAPHS) g_cnt[i] = 1.f / fmaxf(g_cnt[i], 1.f);
}

// ---------------- edge kernel, in_ch = 32 (512 thr, R6 design) --------------
template <int LAYER>
__global__ __launch_bounds__(512, 2)
void edge_kernel32(const float* __restrict__ x0,
                   const int*   __restrict__ ei,
                   const float* __restrict__ ea,
                   const float* __restrict__ We,
                   const float* __restrict__ be) {
    const float* h_in = x0;
    constexpr int IN_CH = 32;
    constexpr int G   = 16;
    constexpr int NI  = 2;
    constexpr int EPB = 8;
    constexpr int XV  = EPB * IN_CH;

    extern __shared__ __align__(16) char smem_raw[];
    ull (*s_part)[EPB][32][18] = reinterpret_cast<ull(*)[EPB][32][18]>(smem_raw);

    __shared__ __align__(16) float s_x[2][EPB][G][NI];   // transposed 0.5*x
    __shared__ __align__(16) float4 s_ea[2][EPB][2];     // raw ea
    __shared__ int s_dst[2][EPB];
    __shared__ int s_rdst[2][EPB];

    const int tid = threadIdx.x;
    const int g   = tid & 15;
    const int op  = tid >> 4;
    const int o0  = op * 2;

    if (blockIdx.x == 0 && tid < 2 * HID) g_bn[tid] = 0.f;

    ull w2[NI][8];
    ull b2[NI];
#pragma unroll
    for (int ii = 0; ii < NI; ii++) {
        const int i = g + ii * G;
        b2[ii] = pack2(be[i * HID + o0], be[i * HID + o0 + 1]);
#pragma unroll
        for (int d = 0; d < 8; d++) {
            const float* p = We + (d * IN_CH + i) * HID + o0;
            w2[ii][d] = pack2(p[0], p[1]);
        }
    }

    const int stride = gridDim.x * EPB;
    const int base   = blockIdx.x * EPB;
    const int xk = tid / IN_CH, xj = tid % IN_CH;
    const int ek = tid >> 3,    ed = tid & 7;
    const int re   = tid >> 6;
    const int rop  = (tid & 63) >> 1;
    const int half = tid & 1;

    float rx = 0.f, rea = 0.f;
    int   rdst = 0;
    if (tid < XV) { const int e = base + xk; if (e < N_EDGES) rx = h_in[ei[e] * IN_CH + xj]; }
    if (tid < 64) { const int e = base + ek; if (e < N_EDGES) rea = ea[e * EDGE_DIM + ed]; }
    if (tid < EPB){ const int e = base + tid; if (e < N_EDGES) rdst = ei[N_EDGES + e]; }
    if (tid < XV) s_x[0][xk][xj & 15][xj >> 4] = rx * 0.5f;
    if (tid < 64) ((float*)s_ea[0])[tid] = rea;
    if (tid < EPB) s_dst[0][tid] = rdst;
    {
        const int b1 = base + stride;
        if (tid < XV) { const int e = b1 + xk; if (e < N_EDGES) rx = h_in[ei[e] * IN_CH + xj]; }
        if (tid < 64) { const int e = b1 + ek; if (e < N_EDGES) rea = ea[e * EDGE_DIM + ed]; }
        if (tid < EPB){ const int e = b1 + tid; if (e < N_EDGES) rdst = ei[N_EDGES + e]; }
    }
    __syncthreads();

    int p = 0;
    int e0 = base;
    for (; e0 < N_EDGES; e0 += stride, p ^= 1) {
        if (tid < EPB) s_rdst[p][tid] = s_dst[p][tid];

        if (tid < XV) s_x[p ^ 1][xk][xj & 15][xj >> 4] = rx * 0.5f;
        if (tid < 64) ((float*)s_ea[p ^ 1])[tid] = rea;
        if (tid < EPB) s_dst[p ^ 1][tid] = rdst;

        {
            const int b2i = e0 + 2 * stride;
            if (tid < XV) { const int e = b2i + xk; if (e < N_EDGES) rx = h_in[ei[e] * IN_CH + xj]; }
            if (tid < 64) { const int e = b2i + ek; if (e < N_EDGES) rea = ea[e * EDGE_DIM + ed]; }
            if (tid < EPB){ const int e = b2i + tid; if (e < N_EDGES) rdst = ei[N_EDGES + e]; }
        }

#pragma unroll
        for (int kk = 0; kk < EPB; kk++) {
            const float4 ev0 = s_ea[p][kk][0];
            const float4 ev1 = s_ea[p][kk][1];
            ull a2[8];
            a2[0] = dup2(ev0.x); a2[1] = dup2(ev0.y);
            a2[2] = dup2(ev0.z); a2[3] = dup2(ev0.w);
            a2[4] = dup2(ev1.x); a2[5] = dup2(ev1.y);
            a2[6] = dup2(ev1.z); a2[7] = dup2(ev1.w);

            const float2 xv = *(const float2*)&s_x[p][kk][g][0];
            ull xd[2]; xd[0] = dup2(xv.x); xd[1] = dup2(xv.y);

            ull sumA = 0ULL, sumB = 0ULL;
#pragma unroll
            for (int ii = 0; ii < NI; ii++) {
                ull t0 = b2[ii];
                ull t1 = fma2(a2[4], w2[ii][4], 0ULL);
#pragma unroll
                for (int d = 0; d < 4; d++) t0 = fma2(a2[d], w2[ii][d], t0);
#pragma unroll
                for (int d = 5; d < 8; d++) t1 = fma2(a2[d], w2[ii][d], t1);
                ull t = add2(t0, t1);
                ull r = add2(t, t & ABS2);
                if (ii & 1) sumB = fma2(xd[ii], r, sumB);
                else        sumA = fma2(xd[ii], r, sumA);
            }
            s_part[p][kk][op][g] = add2(sumA, sumB);
        }

        if (e0 != base) {
            const ulonglong2* q = (const ulonglong2*)&s_part[p ^ 1][re][rop][half * 8];
            ulonglong2 q0 = q[0], q1 = q[1], q2 = q[2], q3 = q[3];
            ull acc = add2(add2(add2(q0.x, q0.y), add2(q1.x, q1.y)),
                           add2(add2(q2.x, q2.y), add2(q3.x, q3.y)));
            float al, ah;
            unpack2(acc, al, ah);
            al += __shfl_xor_sync(0xffffffffu, al, 1);
            ah += __shfl_xor_sync(0xffffffffu, ah, 1);
            const int ep = e0 - stride + re;
            if (ep < N_EDGES) {
                const float v = half ? ah : al;
                atomicAdd(&g_aggr[s_rdst[p ^ 1][re] * HID + rop * 2 + half], v);
            }
        }
        __syncthreads();
    }

    {   // epilogue
        const ulonglong2* q = (const ulonglong2*)&s_part[p ^ 1][re][rop][half * 8];
        ulonglong2 q0 = q[0], q1 = q[1], q2 = q[2], q3 = q[3];
        ull acc = add2(add2(add2(q0.x, q0.y), add2(q1.x, q1.y)),
                       add2(add2(q2.x, q2.y), add2(q3.x, q3.y)));
        float al, ah;
        unpack2(acc, al, ah);
        al += __shfl_xor_sync(0xffffffffu, al, 1);
        ah += __shfl_xor_sync(0xffffffffu, ah, 1);
        const int ep = e0 - stride + re;
        if (ep < N_EDGES) {
            const float v = half ? ah : al;
            atomicAdd(&g_aggr[s_rdst[p ^ 1][re] * HID + rop * 2 + half], v);
        }
    }
}

// ---------------- edge kernel, in_ch = 64 (1024 thr, dual i-half) -----------
// Thread (ih, op, g): ih = tid>>9, op = (tid>>4)&31, g = tid&15, gg = ih*16+g.
// Each thread covers i in {gg, gg+32} (NI=2) -> only 32 weight regs, so a
// 1024-thread block fits the 64-reg cap -> 32 warps/SM (2x R6 occupancy).
// s_part row stride 34 (EVEN) so the reduce's LDS.128 at half*16 is 16B-aligned.
template <int LAYER>
__global__ __launch_bounds__(1024, 1)
void edge_kernel64(const int*   __restrict__ ei,
                   const float* __restrict__ ea,
                   const float* __restrict__ We,
                   const float* __restrict__ be) {
    const float* h_in = (LAYER == 1) ? g_h1 : g_h2;
    constexpr int IN_CH = 64;
    constexpr int EPB = 8;
    constexpr int XV  = EPB * IN_CH;   // 512

    extern __shared__ __align__(16) char smem_raw[];
    ull (*s_part)[EPB][32][34] = reinterpret_cast<ull(*)[EPB][32][34]>(smem_raw);

    __shared__ __align__(16) float s_xT[2][EPB][32][2];  // (0.5*x[i], 0.5*x[i+32])
    __shared__ __align__(16) ull s_ea2[2][EPB][8];       // duplicated ea
    __shared__ int s_dst[2][EPB];
    __shared__ int s_rdst[2][EPB];

    const int tid = threadIdx.x;
    const int g   = tid & 15;
    const int op  = (tid >> 4) & 31;
    const int ih  = tid >> 9;
    const int gg  = ih * 16 + g;       // 0..31
    const int o0  = op * 2;

    if (blockIdx.x == 0 && tid < 2 * HID) g_bn[tid] = 0.f;

    ull w2[2][8];
    ull b2[2];
#pragma unroll
    for (int ii = 0; ii < 2; ii++) {
        const int i = gg + ii * 32;
        b2[ii] = pack2(be[i * HID + o0], be[i * HID + o0 + 1]);
#pragma unroll
        for (int d = 0; d < 8; d++) {
            const float* p = We + (d * IN_CH + i) * HID + o0;
            w2[ii][d] = pack2(p[0], p[1]);
        }
    }

    const int stride = gridDim.x * EPB;
    const int base   = blockIdx.x * EPB;
    const int xk = tid >> 6, xj = tid & 63;      // x loaders: tid < 512
    const int ek = tid >> 3, ed = tid & 7;       // ea loaders: tid < 64
    const int re   = tid >> 6;                   // reduce: tid < 512
    const int rop  = (tid & 63) >> 1;
    const int half = tid & 1;

    float rx = 0.f, rea = 0.f;
    int   rdst = 0;
    if (tid < XV) { const int e = base + xk; if (e < N_EDGES) rx = h_in[ei[e] * IN_CH + xj]; }
    if (tid < 64) { const int e = base + ek; if (e < N_EDGES) rea = ea[e * EDGE_DIM + ed]; }
    if (tid < EPB){ const int e = base + tid; if (e < N_EDGES) rdst = ei[N_EDGES + e]; }
    if (tid < XV) s_xT[0][xk][xj & 31][xj >> 5] = rx * 0.5f;
    if (tid < 64) s_ea2[0][ek][ed] = dup2(rea);
    if (tid < EPB) s_dst[0][tid] = rdst;
    {
        const int b1 = base + stride;
        if (tid < XV) { const int e = b1 + xk; if (e < N_EDGES) rx = h_in[ei[e] * IN_CH + xj]; }
        if (tid < 64) { const int e = b1 + ek; if (e < N_EDGES) rea = ea[e * EDGE_DIM + ed]; }
        if (tid < EPB){ const int e = b1 + tid; if (e < N_EDGES) rdst = ei[N_EDGES + e]; }
    }
    __syncthreads();

    int p = 0;
    int e0 = base;
    for (; e0 < N_EDGES; e0 += stride, p ^= 1) {
        if (tid < EPB) s_rdst[p][tid] = s_dst[p][tid];

        if (tid < XV) s_xT[p ^ 1][xk][xj & 31][xj >> 5] = rx * 0.5f;
        if (tid < 64) s_ea2[p ^ 1][ek][ed] = dup2(rea);
        if (tid < EPB) s_dst[p ^ 1][tid] = rdst;

        {
            const int b2i = e0 + 2 * stride;
            if (tid < XV) { const int e = b2i + xk; if (e < N_EDGES) rx = h_in[ei[e] * IN_CH + xj]; }
            if (tid < 64) { const int e = b2i + ek; if (e < N_EDGES) rea = ea[e * EDGE_DIM + ed]; }
            if (tid < EPB){ const int e = b2i + tid; if (e < N_EDGES) rdst = ei[N_EDGES + e]; }
        }

#pragma unroll
        for (int kk = 0; kk < EPB; kk++) {
            const ulonglong2* eap = (const ulonglong2*)s_ea2[p][kk];
            const ulonglong2 v0 = eap[0], v1 = eap[1], v2 = eap[2], v3 = eap[3];

            const float2 xv = *(const float2*)&s_xT[p][kk][gg][0];
            const ull xd0 = dup2(xv.x), xd1 = dup2(xv.y);

            ull t0 = b2[0];
            ull t1 = fma2(v2.x, w2[0][4], 0ULL);
            t0 = fma2(v0.x, w2[0][0], t0);
            t0 = fma2(v0.y, w2[0][1], t0);
            t0 = fma2(v1.x, w2[0][2], t0);
            t0 = fma2(v1.y, w2[0][3], t0);
            t1 = fma2(v2.y, w2[0][5], t1);
            t1 = fma2(v3.x, w2[0][6], t1);
            t1 = fma2(v3.y, w2[0][7], t1);
            ull ta = add2(t0, t1);
            ull ra = add2(ta, ta & ABS2);                 // 2*relu
            ull sumA = fma2(xd0, ra, 0ULL);

            ull u0 = b2[1];
            ull u1 = fma2(v2.x, w2[1][4], 0ULL);
            u0 = fma2(v0.x, w2[1][0], u0);
            u0 = fma2(v0.y, w2[1][1], u0);
            u0 = fma2(v1.x, w2[1][2], u0);
            u0 = fma2(v1.y, w2[1][3], u0);
            u1 = fma2(v2.y, w2[1][5], u1);
            u1 = fma2(v3.x, w2[1][6], u1);
            u1 = fma2(v3.y, w2[1][7], u1);
            ull tb = add2(u0, u1);
            ull rb = add2(tb, tb & ABS2);
            ull sum = fma2(xd1, rb, sumA);

            s_part[p][kk][op][gg] = sum;
        }

        // reduce previous batch (threads 0..511), overlapped with compute
        if (e0 != base && tid < 512) {
            const ulonglong2* q = (const ulonglong2*)&s_part[p ^ 1][re][rop][half * 16];
            ull acc = 0ULL;
#pragma unroll
            for (int j = 0; j < 8; j++) {
                ulonglong2 qq = q[j];
                acc = add2(acc, add2(qq.x, qq.y));
            }
            float al, ah;
            unpack2(acc, al, ah);
            al += __shfl_xor_sync(0xffffffffu, al, 1);
            ah += __shfl_xor_sync(0xffffffffu, ah, 1);
            const int ep = e0 - stride + re;
            if (ep < N_EDGES) {
                const float v = half ? ah : al;
                atomicAdd(&g_aggr[s_rdst[p ^ 1][re] * HID + rop * 2 + half], v);
            }
        }
        __syncthreads();
    }

    // epilogue: reduce final batch
    if (tid < 512) {
        const ulonglong2* q = (const ulonglong2*)&s_part[p ^ 1][re][rop][half * 16];
        ull acc = 0ULL;
#pragma unroll
        for (int j = 0; j < 8; j++) {
            ulonglong2 qq = q[j];
            acc = add2(acc, add2(qq.x, qq.y));
        }
        float al, ah;
        unpack2(acc, al, ah);
        al += __shfl_xor_sync(0xffffffffu, al, 1);
        ah += __shfl_xor_sync(0xffffffffu, ah, 1);
        const int ep = e0 - stride + re;
        if (ep < N_EDGES) {
            const float v = half ? ah : al;
            atomicAdd(&g_aggr[s_rdst[p ^ 1][re] * HID + rop * 2 + half], v);
        }
    }
}

// ---------------- node kernel: mean-aggr + root linear + bias, BN stats -----
template <int IN_CH, int LAYER>
__global__ __launch_bounds__(256)
void node_kernel(const float* __restrict__ x0,
                 const float* __restrict__ root,
                 const float* __restrict__ bias) {
    const float* h_in = (LAYER == 0) ? x0 : (LAYER == 1 ? g_h1 : g_h2);
    float* h_out = (LAYER == 1) ? g_h2 : g_h1;

    __shared__ float s_root[IN_CH * HID];
    for (int i = threadIdx.x; i < IN_CH * HID; i += 256) s_root[i] = root[i];
    __syncthreads();

    const int oq  = threadIdx.x & 15;
    const int o4  = oq * 4;
    const int sub = threadIdx.x >> 4;
    const float4 bias4 = *(const float4*)(bias + o4);

    float4 bsum = {0.f, 0.f, 0.f, 0.f};
    float4 bsq  = {0.f, 0.f, 0.f, 0.f};

    for (int v = blockIdx.x * 16 + sub; v < N_NODES; v += gridDim.x * 16) {
        const float4* hv4 = (const float4*)(h_in + v * IN_CH);
        float4 s = {0.f, 0.f, 0.f, 0.f};
#pragma unroll
        for (int j = 0; j < IN_CH / 4; j++) {
            const float4 h4 = hv4[j];
            const float4 r0 = *(const float4*)&s_root[(4 * j + 0) * HID + o4];
            const float4 r1 = *(const float4*)&s_root[(4 * j + 1) * HID + o4];
            const float4 r2 = *(const float4*)&s_root[(4 * j + 2) * HID + o4];
            const float4 r3 = *(const float4*)&s_root[(4 * j + 3) * HID + o4];
            s.x = fmaf(h4.x, r0.x, s.x); s.y = fmaf(h4.x, r0.y, s.y);
            s.z = fmaf(h4.x, r0.z, s.z); s.w = fmaf(h4.x, r0.w, s.w);
            s.x = fmaf(h4.y, r1.x, s.x); s.y = fmaf(h4.y, r1.y, s.y);
            s.z = fmaf(h4.y, r1.z, s.z); s.w = fmaf(h4.y, r1.w, s.w);
            s.x = fmaf(h4.z, r2.x, s.x); s.y = fmaf(h4.z, r2.y, s.y);
            s.z = fmaf(h4.z, r2.z, s.z); s.w = fmaf(h4.z, r2.w, s.w);
            s.x = fmaf(h4.w, r3.x, s.x); s.y = fmaf(h4.w, r3.y, s.y);
            s.z = fmaf(h4.w, r3.z, s.z); s.w = fmaf(h4.w, r3.w, s.w);
        }
        const float inv = g_deg[v];
        float4* agp = (float4*)&g_aggr[v * HID + o4];
        const float4 ag = *agp;
        float4 pre;
        pre.x = fmaf(ag.x, inv, s.x) + bias4.x;
        pre.y = fmaf(ag.y, inv, s.y) + bias4.y;
        pre.z = fmaf(ag.z, inv, s.z) + bias4.z;
        pre.w = fmaf(ag.w, inv, s.w) + bias4.w;
        *(float4*)&h_out[v * HID + o4] = pre;
        *agp = make_float4(0.f, 0.f, 0.f, 0.f);
        bsum.x += pre.x; bsum.y += pre.y; bsum.z += pre.z; bsum.w += pre.w;
        bsq.x = fmaf(pre.x, pre.x, bsq.x); bsq.y = fmaf(pre.y, pre.y, bsq.y);
        bsq.z = fmaf(pre.z, pre.z, bsq.z); bsq.w = fmaf(pre.w, pre.w, bsq.w);
    }

    __shared__ float s_sum[HID], s_sq[HID];
    if (threadIdx.x < HID) { s_sum[threadIdx.x] = 0.f; s_sq[threadIdx.x] = 0.f; }
    __syncthreads();
    atomicAdd(&s_sum[o4 + 0], bsum.x); atomicAdd(&s_sum[o4 + 1], bsum.y);
    atomicAdd(&s_sum[o4 + 2], bsum.z); atomicAdd(&s_sum[o4 + 3], bsum.w);
    atomicAdd(&s_sq[o4 + 0], bsq.x);   atomicAdd(&s_sq[o4 + 1], bsq.y);
    atomicAdd(&s_sq[o4 + 2], bsq.z);   atomicAdd(&s_sq[o4 + 3], bsq.w);
    __syncthreads();
    if (threadIdx.x < HID) {
        atomicAdd(&g_bn[threadIdx.x], s_sum[threadIdx.x]);
        atomicAdd(&g_bn[HID + threadIdx.x], s_sq[threadIdx.x]);
    }
}

// ---------------- BN (train-mode, biased var) + ReLU ------------------------
template <int LAYER>
__global__ __launch_bounds__(256)
void bn_kernel(const float* __restrict__ gamma,
               const float* __restrict__ beta,
               const int* __restrict__ batch) {
    float* h = (LAYER == 1) ? g_h2 : g_h1;
    __shared__ float s_scale[HID], s_shift[HID];
    if (threadIdx.x < HID) {
        const int o = threadIdx.x;
        const float inv_n = 1.f / (float)N_NODES;
        const float mu  = g_bn[o] * inv_n;
        const float var = g_bn[HID + o] * inv_n - mu * mu;
        const float sc  = rsqrtf(var + BN_EPS) * gamma[o];
        s_scale[o] = sc;
        s_shift[o] = beta[o] - mu * sc;
    }
    __syncthreads();

    const int i = blockIdx.x * 256 + threadIdx.x;   // quad index
    if (i >= N_NODES * 16) return;
    const int o4 = (i & 15) * 4;
    const int v  = i >> 4;
    float4 h4 = *(float4*)&h[i * 4];
    h4.x = fmaxf(fmaf(h4.x, s_scale[o4 + 0], s_shift[o4 + 0]), 0.f);
    h4.y = fmaxf(fmaf(h4.y, s_scale[o4 + 1], s_shift[o4 + 1]), 0.f);
    h4.z = fmaxf(fmaf(h4.z, s_scale[o4 + 2], s_shift[o4 + 2]), 0.f);
    h4.w = fmaxf(fmaf(h4.w, s_scale[o4 + 3], s_shift[o4 + 3]), 0.f);
    if (LAYER == 2) {
        float* pp = &g_pool[batch[v] * HID + o4];
        atomicAdd(pp + 0, h4.x); atomicAdd(pp + 1, h4.y);
        atomicAdd(pp + 2, h4.z); atomicAdd(pp + 3, h4.w);
    } else {
        *(float4*)&h[i * 4] = h4;
    }
}

// ---------------- head ----------------
__global__ void k_head(const float* __restrict__ Wh,
                       const float* __restrict__ bh,
                       float* __restrict__ out) {
    const int i = blockIdx.x * 256 + threadIdx.x;
    if (i >= N_GRAPHS * N_TASKS) return;
    const int gph = i / N_TASKS;
    const int t   = i % N_TASKS;
    const float inv = g_cnt[gph];
    float s = bh[t];
#pragma unroll
    for (int c = 0; c < HID; c++)
        s = fmaf(g_pool[gph * HID + c] * inv, Wh[c * N_TASKS + t], s);
    out[i] = s;
}

// ---------------- launch ----------------
extern "C" void kernel_launch(void* const* d_in, const int* in_sizes, int n_in,
                              void* d_out, int out_size) {
    const float* x     = (const float*)d_in[0];
    const int*   ei    = (const int*)d_in[1];
    const float* ea    = (const float*)d_in[2];
    const int*   batch = (const int*)d_in[3];
    const float* We[3]    = { (const float*)d_in[4],  (const float*)d_in[10], (const float*)d_in[16] };
    const float* be[3]    = { (const float*)d_in[5],  (const float*)d_in[11], (const float*)d_in[17] };
    const float* root[3]  = { (const float*)d_in[6],  (const float*)d_in[12], (const float*)d_in[18] };
    const float* bias[3]  = { (const float*)d_in[7],  (const float*)d_in[13], (const float*)d_in[19] };
    const float* gamma[3] = { (const float*)d_in[8],  (const float*)d_in[14], (const float*)d_in[20] };
    const float* beta[3]  = { (const float*)d_in[9],  (const float*)d_in[15], (const float*)d_in[21] };
    const float* Wh = (const float*)d_in[22];
    const float* bh = (const float*)d_in[23];
    float* out = (float*)d_out;

    const int IB = (N_GRAPHS * HID + 255) / 256;
    const int CB = (N_EDGES + 255) / 256;
    const int RB = (N_NODES + 255) / 256;
    const int QB = (N_NODES * 16 + 255) / 256;
    const int HB = (N_GRAPHS * N_TASKS + 255) / 256;

    constexpr int SMEM32 = 2 * 8 * 32 * 18 * (int)sizeof(ull);   // 73728 B
    constexpr int SMEM64 = 2 * 8 * 32 * 34 * (int)sizeof(ull);   // 139264 B
    static bool attr_done = false;
    if (!attr_done) {
        cudaFuncSetAttribute(edge_kernel32<0>, cudaFuncAttributeMaxDynamicSharedMemorySize, SMEM32);
        cudaFuncSetAttribute(edge_kernel64<1>, cudaFuncAttributeMaxDynamicSharedMemorySize, SMEM64);
        cudaFuncSetAttribute(edge_kernel64<2>, cudaFuncAttributeMaxDynamicSharedMemorySize, SMEM64);
        attr_done = true;
    }

    k_init<<<IB, 256>>>();
    k_counts<<<CB, 256>>>(ei, batch);
    k_recip<<<RB, 256>>>();

    // layer 0 (in_ch = 32): x -> g_h1
    edge_kernel32<0><<<592, 512, SMEM32>>>(x, ei, ea, We[0], be[0]);
    node_kernel<IN_DIM, 0><<<1184, 256>>>(x, root[0], bias[0]);
    bn_kernel<0><<<QB, 256>>>(gamma[0], beta[0], batch);

    // layer 1 (in_ch = 64): g_h1 -> g_h2
    edge_kernel64<1><<<296, 1024, SMEM64>>>(ei, ea, We[1], be[1]);
    node_kernel<HID, 1><<<1184, 256>>>(x, root[1], bias[1]);
    bn_kernel<1><<<QB, 256>>>(gamma[1], beta[1], batch);

    // layer 2 (in_ch = 64): g_h2 -> g_h1
    edge_kernel64<2><<<296, 1024, SMEM64>>>(ei, ea, We[2], be[2]);
    node_kernel<HID, 2><<<1184, 256>>>(x, root[2], bias[2]);
    bn_kernel<2><<<QB, 256>>>(gamma[2], beta[2], batch);   // fused pool

    k_head<<<HB, 256>>>(Wh, bh, out);
}

// round 10
// speedup vs baseline: 1.1546x; 1.1546x over previous
#include <cuda_runtime.h>
#include <cuda_bf16.h>

// ---------------- problem constants ----------------
constexpr int N_NODES  = 50000;
constexpr int N_EDGES  = 100000;
constexpr int N_GRAPHS = 2000;
constexpr int IN_DIM   = 32;
constexpr int EDGE_DIM = 8;
constexpr int HID      = 64;
constexpr int N_TASKS  = 12;
constexpr float BN_EPS = 1e-5f;

typedef unsigned long long ull;
constexpr ull ABS2 = 0x7FFFFFFF7FFFFFFFULL;

// ---------------- packed f32x2 helpers ----------------
__device__ __forceinline__ ull pack2(float lo, float hi) {
    ull r; asm("mov.b64 %0, {%1,%2};" : "=l"(r) : "f"(lo), "f"(hi)); return r;
}
__device__ __forceinline__ ull dup2(float v) {
    ull r; asm("mov.b64 %0, {%1,%1};" : "=l"(r) : "f"(v)); return r;
}
__device__ __forceinline__ void unpack2(ull v, float& lo, float& hi) {
    asm("mov.b64 {%0,%1}, %2;" : "=f"(lo), "=f"(hi) : "l"(v));
}
__device__ __forceinline__ ull fma2(ull a, ull b, ull c) {
    ull d; asm("fma.rn.f32x2 %0, %1, %2, %3;" : "=l"(d) : "l"(a), "l"(b), "l"(c)); return d;
}
__device__ __forceinline__ ull add2(ull a, ull b) {
    ull d; asm("add.rn.f32x2 %0, %1, %2;" : "=l"(d) : "l"(a), "l"(b)); return d;
}

// ---------------- scratch (device globals; no allocation allowed) -----------
__device__ float g_h1[N_NODES * HID];
__device__ float g_h2[N_NODES * HID];
__device__ float g_aggr[N_NODES * HID];   // zero .bss; node kernels restore zeros
__device__ float g_deg[N_NODES];          // reciprocal after k_recip
__device__ float g_cnt[N_GRAPHS];         // reciprocal after k_recip
__device__ float g_bn[2 * HID];
__device__ float g_pool[N_GRAPHS * HID];

// ---------------- init / counts / recip ----------------
__global__ void k_init() {
    int i = blockIdx.x * 256 + threadIdx.x;
    if (i < N_NODES)        g_deg[i] = 0.f;
    if (i < N_GRAPHS * HID) g_pool[i] = 0.f;
    if (i < N_GRAPHS)       g_cnt[i] = 0.f;
    if (i < 2 * HID)        g_bn[i] = 0.f;
}

__global__ void k_counts(const int* __restrict__ ei, const int* __restrict__ batch) {
    int i = blockIdx.x * 256 + threadIdx.x;
    if (i < N_EDGES) atomicAdd(&g_deg[ei[N_EDGES + i]], 1.f);
    if (i < N_NODES) atomicAdd(&g_cnt[batch[i]], 1.f);
}

__global__ void k_recip() {
    int i = blockIdx.x * 256 + threadIdx.x;
    if (i < N_NODES)  g_deg[i] = 1.f / fmaxf(g_deg[i], 1.f);
    if (i < N_GRAPHS) g_cnt[i] = 1.f / fmaxf(g_cnt[i], 1.f);
}

// ---------------- fused edge kernel (single-barrier pipelined) --------------
// theta[e][i][o] = relu( sum_d ea[e][d]*We[d][i*HID+o] + be[i*HID+o] )
// m[e][o]       = sum_i x_src[i] * theta[e][i][o]  -> atomicAdd to aggr[dst][o]
//
// 512 thr: op = tid>>4 (o-pair), g = tid&15 (i-group of 16). Weights f32x2 in
// regs (NI = IN_CH/16 slices). Single 8-deep fma2 chain per slice (ILP comes
// from NI slices x 8-edge unroll). relu(t)=0.5*(t+|t|), 0.5 folded into x.
// ONE __syncthreads per 8-edge batch: publish i+1, prefetch i+2, compute i,
// reduce i-1 (stable dst via s_rdst), barrier.
template <int IN_CH, int LAYER>
__global__ __launch_bounds__(512, (IN_CH == 32) ? 2 : 1)
void edge_kernel(const float* __restrict__ x0,
                 const int*   __restrict__ ei,
                 const float* __restrict__ ea,
                 const float* __restrict__ We,
                 const float* __restrict__ be) {
    const float* h_in = (LAYER == 0) ? x0 : (LAYER == 1 ? g_h1 : g_h2);
    constexpr int G   = 16;
    constexpr int NI  = IN_CH / G;
    constexpr int EPB = 8;
    constexpr int XV  = EPB * IN_CH;

    extern __shared__ __align__(16) char smem_raw[];
    ull (*s_part)[EPB][32][18] = reinterpret_cast<ull(*)[EPB][32][18]>(smem_raw);

    __shared__ __align__(16) float s_x[2][EPB][G][NI];   // transposed 0.5*x
    __shared__ __align__(16) float4 s_ea[2][EPB][2];     // raw ea (8 floats)
    __shared__ int s_dst[2][EPB];
    __shared__ int s_rdst[2][EPB];                       // stable copy for reduce

    const int tid = threadIdx.x;
    const int g   = tid & 15;
    const int op  = tid >> 4;      // 0..31
    const int o0  = op * 2;

    if (blockIdx.x == 0 && tid < 2 * HID) g_bn[tid] = 0.f;   // for next node pass

    ull w2[NI][8];
    ull b2[NI];
#pragma unroll
    for (int ii = 0; ii < NI; ii++) {
        const int i = g + ii * G;
        b2[ii] = pack2(be[i * HID + o0], be[i * HID + o0 + 1]);
#pragma unroll
        for (int d = 0; d < 8; d++) {
            const float* p = We + (d * IN_CH + i) * HID + o0;
            w2[ii][d] = pack2(p[0], p[1]);
        }
    }

    const int stride = gridDim.x * EPB;
    const int base   = blockIdx.x * EPB;
    const int xk = tid / IN_CH, xj = tid % IN_CH;
    const int ek = tid >> 3,    ed = tid & 7;
    const int re   = tid >> 6;          // edge 0..7
    const int rop  = (tid & 63) >> 1;   // o-pair 0..31
    const int half = tid & 1;           // g-half

    float rx = 0.f, rea = 0.f;
    int   rdst = 0;
    // stage + publish batch 0, then stage batch 1
    if (tid < XV) { const int e = base + xk; if (e < N_EDGES) rx = h_in[ei[e] * IN_CH + xj]; }
    if (tid < 64) { const int e = base + ek; if (e < N_EDGES) rea = ea[e * EDGE_DIM + ed]; }
    if (tid < EPB){ const int e = base + tid; if (e < N_EDGES) rdst = ei[N_EDGES + e]; }
    if (tid < XV) s_x[0][xk][xj & 15][xj >> 4] = rx * 0.5f;
    if (tid < 64) ((float*)s_ea[0])[tid] = rea;
    if (tid < EPB) s_dst[0][tid] = rdst;
    {
        const int b1 = base + stride;
        if (tid < XV) { const int e = b1 + xk; if (e < N_EDGES) rx = h_in[ei[e] * IN_CH + xj]; }
        if (tid < 64) { const int e = b1 + ek; if (e < N_EDGES) rea = ea[e * EDGE_DIM + ed]; }
        if (tid < EPB){ const int e = b1 + tid; if (e < N_EDGES) rdst = ei[N_EDGES + e]; }
    }
    __syncthreads();

    int p = 0;
    int e0 = base;
    for (; e0 < N_EDGES; e0 += stride, p ^= 1) {
        // stable dst copy for next-iteration reduce of this batch
        if (tid < EPB) s_rdst[p][tid] = s_dst[p][tid];

        // publish batch e0+stride into buffer p^1
        if (tid < XV) s_x[p ^ 1][xk][xj & 15][xj >> 4] = rx * 0.5f;
        if (tid < 64) ((float*)s_ea[p ^ 1])[tid] = rea;
        if (tid < EPB) s_dst[p ^ 1][tid] = rdst;

        // prefetch batch e0+2*stride (latency covered by compute)
        {
            const int b2i = e0 + 2 * stride;
            if (tid < XV) { const int e = b2i + xk; if (e < N_EDGES) rx = h_in[ei[e] * IN_CH + xj]; }
            if (tid < 64) { const int e = b2i + ek; if (e < N_EDGES) rea = ea[e * EDGE_DIM + ed]; }
            if (tid < EPB){ const int e = b2i + tid; if (e < N_EDGES) rdst = ei[N_EDGES + e]; }
        }

        // compute batch e0 -> s_part[p]
#pragma unroll
        for (int kk = 0; kk < EPB; kk++) {
            const float4 ev0 = s_ea[p][kk][0];
            const float4 ev1 = s_ea[p][kk][1];
            ull a2[8];
            a2[0] = dup2(ev0.x); a2[1] = dup2(ev0.y);
            a2[2] = dup2(ev0.z); a2[3] = dup2(ev0.w);
            a2[4] = dup2(ev1.x); a2[5] = dup2(ev1.y);
            a2[6] = dup2(ev1.z); a2[7] = dup2(ev1.w);

            ull xd[NI];
            if constexpr (NI == 4) {
                const float4 xv = *(const float4*)&s_x[p][kk][g][0];
                xd[0] = dup2(xv.x); xd[1] = dup2(xv.y);
                xd[2] = dup2(xv.z); xd[3] = dup2(xv.w);
            } else {
                const float2 xv = *(const float2*)&s_x[p][kk][g][0];
                xd[0] = dup2(xv.x); xd[1] = dup2(xv.y);
            }

            ull sumA = 0ULL, sumB = 0ULL;
#pragma unroll
            for (int ii = 0; ii < NI; ii++) {
                ull t = b2[ii];
#pragma unroll
                for (int d = 0; d < 8; d++) t = fma2(a2[d], w2[ii][d], t);
                ull r = add2(t, t & ABS2);                  // 2*relu(t)
                if (ii & 1) sumB = fma2(xd[ii], r, sumB);   // (0.5x)*(2relu)
                else        sumA = fma2(xd[ii], r, sumA);
            }
            s_part[p][kk][op][g] = (NI > 1) ? add2(sumA, sumB) : sumA;
        }

        // reduce batch e0-stride from s_part[p^1] (overlaps other warps' compute)
        if (e0 != base) {
            const ulonglong2* q = (const ulonglong2*)&s_part[p ^ 1][re][rop][half * 8];
            ulonglong2 q0 = q[0], q1 = q[1], q2 = q[2], q3 = q[3];
            ull acc = add2(add2(add2(q0.x, q0.y), add2(q1.x, q1.y)),
                           add2(add2(q2.x, q2.y), add2(q3.x, q3.y)));
            float al, ah;
            unpack2(acc, al, ah);
            al += __shfl_xor_sync(0xffffffffu, al, 1);
            ah += __shfl_xor_sync(0xffffffffu, ah, 1);
            const int ep = e0 - stride + re;
            if (ep < N_EDGES) {
                const float v = half ? ah : al;
                atomicAdd(&g_aggr[s_rdst[p ^ 1][re] * HID + rop * 2 + half], v);
            }
        }
        __syncthreads();
    }

    // epilogue: reduce the final computed batch
    {
        const ulonglong2* q = (const ulonglong2*)&s_part[p ^ 1][re][rop][half * 8];
        ulonglong2 q0 = q[0], q1 = q[1], q2 = q[2], q3 = q[3];
        ull acc = add2(add2(add2(q0.x, q0.y), add2(q1.x, q1.y)),
                       add2(add2(q2.x, q2.y), add2(q3.x, q3.y)));
        float al, ah;
        unpack2(acc, al, ah);
        al += __shfl_xor_sync(0xffffffffu, al, 1);
        ah += __shfl_xor_sync(0xffffffffu, ah, 1);
        const int ep = e0 - stride + re;
        if (ep < N_EDGES) {
            const float v = half ? ah : al;
            atomicAdd(&g_aggr[s_rdst[p ^ 1][re] * HID + rop * 2 + half], v);
        }
    }
}

// ---------------- node kernel: mean-aggr + root linear + bias, BN stats -----
template <int IN_CH, int LAYER>
__global__ __launch_bounds__(256)
void node_kernel(const float* __restrict__ x0,
                 const float* __restrict__ root,
                 const float* __restrict__ bias) {
    const float* h_in = (LAYER == 0) ? x0 : (LAYER == 1 ? g_h1 : g_h2);
    float* h_out = (LAYER == 1) ? g_h2 : g_h1;

    __shared__ float s_root[IN_CH * HID];
    for (int i = threadIdx.x; i < IN_CH * HID; i += 256) s_root[i] = root[i];
    __syncthreads();

    const int oq  = threadIdx.x & 15;
    const int o4  = oq * 4;
    const int sub = threadIdx.x >> 4;
    const float4 bias4 = *(const float4*)(bias + o4);

    float4 bsum = {0.f, 0.f, 0.f, 0.f};
    float4 bsq  = {0.f, 0.f, 0.f, 0.f};

    for (int v = blockIdx.x * 16 + sub; v < N_NODES; v += gridDim.x * 16) {
        const float4* hv4 = (const float4*)(h_in + v * IN_CH);
        float4 s = {0.f, 0.f, 0.f, 0.f};
#pragma unroll
        for (int j = 0; j < IN_CH / 4; j++) {
            const float4 h4 = hv4[j];
            const float4 r0 = *(const float4*)&s_root[(4 * j + 0) * HID + o4];
            const float4 r1 = *(const float4*)&s_root[(4 * j + 1) * HID + o4];
            const float4 r2 = *(const float4*)&s_root[(4 * j + 2) * HID + o4];
            const float4 r3 = *(const float4*)&s_root[(4 * j + 3) * HID + o4];
            s.x = fmaf(h4.x, r0.x, s.x); s.y = fmaf(h4.x, r0.y, s.y);
            s.z = fmaf(h4.x, r0.z, s.z); s.w = fmaf(h4.x, r0.w, s.w);
            s.x = fmaf(h4.y, r1.x, s.x); s.y = fmaf(h4.y, r1.y, s.y);
            s.z = fmaf(h4.y, r1.z, s.z); s.w = fmaf(h4.y, r1.w, s.w);
            s.x = fmaf(h4.z, r2.x, s.x); s.y = fmaf(h4.z, r2.y, s.y);
            s.z = fmaf(h4.z, r2.z, s.z); s.w = fmaf(h4.z, r2.w, s.w);
            s.x = fmaf(h4.w, r3.x, s.x); s.y = fmaf(h4.w, r3.y, s.y);
            s.z = fmaf(h4.w, r3.z, s.z); s.w = fmaf(h4.w, r3.w, s.w);
        }
        const float inv = g_deg[v];
        float4* agp = (float4*)&g_aggr[v * HID + o4];
        const float4 ag = *agp;
        float4 pre;
        pre.x = fmaf(ag.x, inv, s.x) + bias4.x;
        pre.y = fmaf(ag.y, inv, s.y) + bias4.y;
        pre.z = fmaf(ag.z, inv, s.z) + bias4.z;
        pre.w = fmaf(ag.w, inv, s.w) + bias4.w;
        *(float4*)&h_out[v * HID + o4] = pre;
        *agp = make_float4(0.f, 0.f, 0.f, 0.f);
        bsum.x += pre.x; bsum.y += pre.y; bsum.z += pre.z; bsum.w += pre.w;
        bsq.x = fmaf(pre.x, pre.x, bsq.x); bsq.y = fmaf(pre.y, pre.y, bsq.y);
        bsq.z = fmaf(pre.z, pre.z, bsq.z); bsq.w = fmaf(pre.w, pre.w, bsq.w);
    }

    __shared__ float s_sum[HID], s_sq[HID];
    if (threadIdx.x < HID) { s_sum[threadIdx.x] = 0.f; s_sq[threadIdx.x] = 0.f; }
    __syncthreads();
    atomicAdd(&s_sum[o4 + 0], bsum.x); atomicAdd(&s_sum[o4 + 1], bsum.y);
    atomicAdd(&s_sum[o4 + 2], bsum.z); atomicAdd(&s_sum[o4 + 3], bsum.w);
    atomicAdd(&s_sq[o4 + 0], bsq.x);   atomicAdd(&s_sq[o4 + 1], bsq.y);
    atomicAdd(&s_sq[o4 + 2], bsq.z);   atomicAdd(&s_sq[o4 + 3], bsq.w);
    __syncthreads();
    if (threadIdx.x < HID) {
        atomicAdd(&g_bn[threadIdx.x], s_sum[threadIdx.x]);
        atomicAdd(&g_bn[HID + threadIdx.x], s_sq[threadIdx.x]);
    }
}

// ---------------- BN (train-mode, biased var) + ReLU ------------------------
template <int LAYER>
__global__ __launch_bounds__(256)
void bn_kernel(const float* __restrict__ gamma,
               const float* __restrict__ beta,
               const int* __restrict__ batch) {
    float* h = (LAYER == 1) ? g_h2 : g_h1;
    __shared__ float s_scale[HID], s_shift[HID];
    if (threadIdx.x < HID) {
        const int o = threadIdx.x;
        const float inv_n = 1.f / (float)N_NODES;
        const float mu  = g_bn[o] * inv_n;
        const float var = g_bn[HID + o] * inv_n - mu * mu;
        const float sc  = rsqrtf(var + BN_EPS) * gamma[o];
        s_scale[o] = sc;
        s_shift[o] = beta[o] - mu * sc;
    }
    __syncthreads();

    const int i = blockIdx.x * 256 + threadIdx.x;   // quad index
    if (i >= N_NODES * 16) return;
    const int o4 = (i & 15) * 4;
    const int v  = i >> 4;
    float4 h4 = *(float4*)&h[i * 4];
    h4.x = fmaxf(fmaf(h4.x, s_scale[o4 + 0], s_shift[o4 + 0]), 0.f);
    h4.y = fmaxf(fmaf(h4.y, s_scale[o4 + 1], s_shift[o4 + 1]), 0.f);
    h4.z = fmaxf(fmaf(h4.z, s_scale[o4 + 2], s_shift[o4 + 2]), 0.f);
    h4.w = fmaxf(fmaf(h4.w, s_scale[o4 + 3], s_shift[o4 + 3]), 0.f);
    if (LAYER == 2) {
        float* pp = &g_pool[batch[v] * HID + o4];
        atomicAdd(pp + 0, h4.x); atomicAdd(pp + 1, h4.y);
        atomicAdd(pp + 2, h4.z); atomicAdd(pp + 3, h4.w);
    } else {
        *(float4*)&h[i * 4] = h4;
    }
}

// ---------------- head ----------------
__global__ void k_head(const float* __restrict__ Wh,
                       const float* __restrict__ bh,
                       float* __restrict__ out) {
    const int i = blockIdx.x * 256 + threadIdx.x;
    if (i >= N_GRAPHS * N_TASKS) return;
    const int gph = i / N_TASKS;
    const int t   = i % N_TASKS;
    const float inv = g_cnt[gph];
    float s = bh[t];
#pragma unroll
    for (int c = 0; c < HID; c++)
        s = fmaf(g_pool[gph * HID + c] * inv, Wh[c * N_TASKS + t], s);
    out[i] = s;
}

// ---------------- launch ----------------
extern "C" void kernel_launch(void* const* d_in, const int* in_sizes, int n_in,
                              void* d_out, int out_size) {
    const float* x     = (const float*)d_in[0];
    const int*   ei    = (const int*)d_in[1];
    const float* ea    = (const float*)d_in[2];
    const int*   batch = (const int*)d_in[3];
    const float* We[3]    = { (const float*)d_in[4],  (const float*)d_in[10], (const float*)d_in[16] };
    const float* be[3]    = { (const float*)d_in[5],  (const float*)d_in[11], (const float*)d_in[17] };
    const float* root[3]  = { (const float*)d_in[6],  (const float*)d_in[12], (const float*)d_in[18] };
    const float* bias[3]  = { (const float*)d_in[7],  (const float*)d_in[13], (const float*)d_in[19] };
    const float* gamma[3] = { (const float*)d_in[8],  (const float*)d_in[14], (const float*)d_in[20] };
    const float* beta[3]  = { (const float*)d_in[9],  (const float*)d_in[15], (const float*)d_in[21] };
    const float* Wh = (const float*)d_in[22];
    const float* bh = (const float*)d_in[23];
    float* out = (float*)d_out;

    const int IB = (N_GRAPHS * HID + 255) / 256;
    const int CB = (N_EDGES + 255) / 256;
    const int RB = (N_NODES + 255) / 256;
    const int QB = (N_NODES * 16 + 255) / 256;
    const int HB = (N_GRAPHS * N_TASKS + 255) / 256;

    constexpr int PART_SMEM = 2 * 8 * 32 * 18 * (int)sizeof(ull);   // 73728 B
    static bool attr_done = false;
    if (!attr_done) {
        cudaFuncSetAttribute(edge_kernel<IN_DIM, 0>, cudaFuncAttributeMaxDynamicSharedMemorySize, PART_SMEM);
        cudaFuncSetAttribute(edge_kernel<HID, 1>,   cudaFuncAttributeMaxDynamicSharedMemorySize, PART_SMEM);
        cudaFuncSetAttribute(edge_kernel<HID, 2>,   cudaFuncAttributeMaxDynamicSharedMemorySize, PART_SMEM);
        attr_done = true;
    }

    k_init<<<IB, 256>>>();
    k_counts<<<CB, 256>>>(ei, batch);
    k_recip<<<RB, 256>>>();

    // layer 0 (in_ch = 32): x -> g_h1
    edge_kernel<IN_DIM, 0><<<592, 512, PART_SMEM>>>(x, ei, ea, We[0], be[0]);
    node_kernel<IN_DIM, 0><<<1184, 256>>>(x, root[0], bias[0]);
    bn_kernel<0><<<QB, 256>>>(gamma[0], beta[0], batch);

    // layer 1 (in_ch = 64): g_h1 -> g_h2
    edge_kernel<HID, 1><<<592, 512, PART_SMEM>>>(x, ei, ea, We[1], be[1]);
    node_kernel<HID, 1><<<1184, 256>>>(x, root[1], bias[1]);
    bn_kernel<1><<<QB, 256>>>(gamma[1], beta[1], batch);

    // layer 2 (in_ch = 64): g_h2 -> g_h1
    edge_kernel<HID, 2><<<592, 512, PART_SMEM>>>(x, ei, ea, We[2], be[2]);
    node_kernel<HID, 2><<<1184, 256>>>(x, root[2], bias[2]);
    bn_kernel<2><<<QB, 256>>>(gamma[2], beta[2], batch);   // fused pool

    k_head<<<HB, 256>>>(Wh, bh, out);
}